// round 14
// baseline (speedup 1.0000x reference)
#include <cuda_runtime.h>
#include <math.h>

// Inputs (metadata order): y[16M] f32, mu[16M] f32, std[16M] f32, idx[200*100] i32
// Output: 1 x f32 (KL scalar)
//
// CONVERGED FINAL KERNEL — 13 rounds of evidence:
//   - Wall pinned at the harness graph-replay floor: this exact source has
//     measured {8.672, 8.704, 8.928, 8.928} us; sigma ~0.12 us of pure jitter.
//   - No hardware pipe exceeds ~13% in any profile; the kernel's real
//     execution is a ~1-2 us gather-latency chain hidden under the floor.
//   - Reproducible pessimizations (avoided): fp64 single-thread tail (+2.3us),
//     single-warp-per-sample gather (+2.3us, per-warp load-queue waves).
//   - Chain-minimal design: 200 blocks x 128 threads; threads 0..99 gather one
//     (y,mu,sd) triple (coalesced idx row, MLP=3), shfl+smem block reduce,
//     fp32 shifted-moment global atomics (q-K removes variance cancellation),
//     ticketed last block computes KL with fp32 MUFU math.

#define NUM_SAMPLES 200
#define KDOF 100

// Scratch (no device allocation allowed). Winner resets for next graph replay.
__device__ float        g_s1 = 0.0f;   // sum of (q - K)
__device__ float        g_s2 = 0.0f;   // sum of (q - K)^2
__device__ unsigned int g_count = 0;

__global__ void __launch_bounds__(128) fused_chi2_kl_kernel(
    const float* __restrict__ y,
    const float* __restrict__ mu,
    const float* __restrict__ sd,
    const int*   __restrict__ idx,
    float*       __restrict__ out)
{
    const int s = blockIdx.x;
    const int t = threadIdx.x;

    // ---- Phase 1: per-sample chi-square statistic ----
    float v = 0.0f;
    if (t < KDOF) {
        const int i = idx[s * KDOF + t];   // coalesced 400B row, chain head
        // three independent gathers -> MLP=3 per thread
        const float d = __fdividef(y[i] - mu[i], sd[i]);
        v = d * d;
    }

    #pragma unroll
    for (int o = 16; o > 0; o >>= 1)
        v += __shfl_down_sync(0xFFFFFFFFu, v, o);

    __shared__ float sm[4];
    if ((t & 31) == 0) sm[t >> 5] = v;
    __syncthreads();

    if (t != 0) return;

    // Shifted statistic: p = q - K (kills cancellation in the var formula)
    const float p = (sm[0] + sm[1] + sm[2] + sm[3]) - (float)KDOF;

    atomicAdd(&g_s1, p);
    atomicAdd(&g_s2, p * p);
    __threadfence();                            // publish sums before ticket

    if (atomicAdd(&g_count, 1u) != NUM_SAMPLES - 1u) return;

    // ---- Phase 2 (single thread, last block): KL from shifted moments ----
    __threadfence();                            // acquire: see all atomic sums

    const float s1 = g_s1;
    const float s2 = g_s2;

    const float inv_n  = 1.0f / (float)NUM_SAMPLES;
    const float dm     = s1 * inv_n;                          // emp_mu - K
    const float var    = (s2 - s1 * s1 * inv_n)
                         * (1.0f / (float)(NUM_SAMPLES - 1)); // unbiased var
    const float two_k  = 2.0f * (float)KDOF;

    out[0] = 0.5f * __logf(two_k / var)
           + (var + dm * dm) / (2.0f * two_k)
           - 0.5f;

    // Reset scratch for next replay.
    g_s1 = 0.0f;
    g_s2 = 0.0f;
    g_count = 0;
}

extern "C" void kernel_launch(void* const* d_in, const int* in_sizes, int n_in,
                              void* d_out, int out_size)
{
    const float* y   = (const float*)d_in[0];
    const float* mu  = (const float*)d_in[1];
    const float* sd  = (const float*)d_in[2];
    const int*   idx = (const int*)d_in[3];
    float* out = (float*)d_out;

    fused_chi2_kl_kernel<<<NUM_SAMPLES, 128>>>(y, mu, sd, idx, out);
}